// round 2
// baseline (speedup 1.0000x reference)
#include <cuda_runtime.h>
#include <cuda_bf16.h>
#include <math.h>

// Problem constants
#define BATCH 32
#define NTOK  3136
#define DIM   384
#define HEADS 8
#define CH    48            // DIM / HEADS
#define MTOT  (BATCH * NTOK)   // 100352
#define ETOT  (3 * DIM)        // 1152

// Scratch: qkv stored as [e][m] with e = s*384 + h*48 + c, m = b*NTOK + n
__device__ float g_qkv[(size_t)ETOT * MTOT];   // 462 MB
__device__ float g_av [(size_t)DIM  * MTOT];   // 154 MB, attention output [e'][m]

// ---------------------------------------------------------------------------
// GEMM NT:  C[e][m] = sum_k A[e][k] * B[m][k]
// A: [E][K] row-major (weights), B: [M][K] row-major (activations)
// Tiles 128x128x16, 256 threads, 8x8 microtile.
// ---------------------------------------------------------------------------
__global__ void __launch_bounds__(256) gemm_nt_kernel(
    const float* __restrict__ A, const float* __restrict__ B,
    float* __restrict__ C, int E, int M, int K)
{
    __shared__ float As[16][132];
    __shared__ float Bs[16][132];
    const int e0 = blockIdx.y * 128;
    const int m0 = blockIdx.x * 128;
    const int tid = threadIdx.x;
    const int tx = tid & 15, ty = tid >> 4;
    const int lr = tid >> 2, lq = tid & 3;

    float acc[8][8];
#pragma unroll
    for (int i = 0; i < 8; i++)
#pragma unroll
        for (int j = 0; j < 8; j++) acc[i][j] = 0.f;

    for (int k0 = 0; k0 < K; k0 += 16) {
#pragma unroll
        for (int r = 0; r < 2; r++) {
            int row = lr + r * 64;
            float4 v = *(const float4*)(A + (size_t)(e0 + row) * K + k0 + lq * 4);
            As[lq*4+0][row] = v.x; As[lq*4+1][row] = v.y;
            As[lq*4+2][row] = v.z; As[lq*4+3][row] = v.w;
        }
#pragma unroll
        for (int r = 0; r < 2; r++) {
            int row = lr + r * 64;
            float4 v = *(const float4*)(B + (size_t)(m0 + row) * K + k0 + lq * 4);
            Bs[lq*4+0][row] = v.x; Bs[lq*4+1][row] = v.y;
            Bs[lq*4+2][row] = v.z; Bs[lq*4+3][row] = v.w;
        }
        __syncthreads();
#pragma unroll
        for (int kk = 0; kk < 16; kk++) {
            float a[8], b[8];
#pragma unroll
            for (int i = 0; i < 8; i++) a[i] = As[kk][ty*8 + i];
#pragma unroll
            for (int j = 0; j < 8; j++) b[j] = Bs[kk][tx*8 + j];
#pragma unroll
            for (int i = 0; i < 8; i++)
#pragma unroll
                for (int j = 0; j < 8; j++) acc[i][j] += a[i] * b[j];
        }
        __syncthreads();
    }
#pragma unroll
    for (int i = 0; i < 8; i++) {
        size_t off = (size_t)(e0 + ty*8 + i) * M + m0 + tx*8;
        float4 v0 = make_float4(acc[i][0], acc[i][1], acc[i][2], acc[i][3]);
        float4 v1 = make_float4(acc[i][4], acc[i][5], acc[i][6], acc[i][7]);
        *(float4*)(C + off)     = v0;
        *(float4*)(C + off + 4) = v1;
    }
}

// ---------------------------------------------------------------------------
// GEMM TN:  C[m][f] = sum_k At[k][m] * W[f][k] + bias[f]
// At: [K][M] row-major (m contiguous), W: [F][K] row-major
// ---------------------------------------------------------------------------
__global__ void __launch_bounds__(256) gemm_tn_kernel(
    const float* __restrict__ At, const float* __restrict__ W,
    const float* __restrict__ bias, float* __restrict__ C,
    int M, int F, int K)
{
    __shared__ float Xs[16][132];
    __shared__ float Ws[16][132];
    const int m0 = blockIdx.x * 128;
    const int f0 = blockIdx.y * 128;
    const int tid = threadIdx.x;
    const int tx = tid & 15, ty = tid >> 4;
    const int kr = tid >> 4, mq = tid & 15;   // X load
    const int lr = tid >> 2, lq = tid & 3;    // W load

    float acc[8][8];
#pragma unroll
    for (int i = 0; i < 8; i++)
#pragma unroll
        for (int j = 0; j < 8; j++) acc[i][j] = 0.f;

    for (int k0 = 0; k0 < K; k0 += 16) {
        {
            const float* src = At + (size_t)(k0 + kr) * M + m0 + mq * 8;
            float4 x0 = *(const float4*)(src);
            float4 x1 = *(const float4*)(src + 4);
            *(float4*)&Xs[kr][mq*8]     = x0;
            *(float4*)&Xs[kr][mq*8 + 4] = x1;
        }
#pragma unroll
        for (int r = 0; r < 2; r++) {
            int row = lr + r * 64;
            float4 v = *(const float4*)(W + (size_t)(f0 + row) * K + k0 + lq * 4);
            Ws[lq*4+0][row] = v.x; Ws[lq*4+1][row] = v.y;
            Ws[lq*4+2][row] = v.z; Ws[lq*4+3][row] = v.w;
        }
        __syncthreads();
#pragma unroll
        for (int kk = 0; kk < 16; kk++) {
            float a[8], b[8];
#pragma unroll
            for (int i = 0; i < 8; i++) a[i] = Xs[kk][ty*8 + i];
#pragma unroll
            for (int j = 0; j < 8; j++) b[j] = Ws[kk][tx*8 + j];
#pragma unroll
            for (int i = 0; i < 8; i++)
#pragma unroll
                for (int j = 0; j < 8; j++) acc[i][j] += a[i] * b[j];
        }
        __syncthreads();
    }
    float bj[8];
#pragma unroll
    for (int j = 0; j < 8; j++) bj[j] = bias[f0 + tx*8 + j];
#pragma unroll
    for (int i = 0; i < 8; i++) {
        size_t off = (size_t)(m0 + ty*8 + i) * F + f0 + tx*8;
        float4 v0 = make_float4(acc[i][0]+bj[0], acc[i][1]+bj[1], acc[i][2]+bj[2], acc[i][3]+bj[3]);
        float4 v1 = make_float4(acc[i][4]+bj[4], acc[i][5]+bj[5], acc[i][6]+bj[6], acc[i][7]+bj[7]);
        *(float4*)(C + off)     = v0;
        *(float4*)(C + off + 4) = v1;
    }
}

// ---------------------------------------------------------------------------
// L2 normalize q and k rows over n. One block per (e, b) with e in [0, 768).
// Row segment: g_qkv[e*MTOT + b*NTOK .. +NTOK)
// ---------------------------------------------------------------------------
__global__ void __launch_bounds__(256) l2norm_kernel(float* __restrict__ qkv)
{
    const int e = blockIdx.x >> 5;       // 0..767
    const int b = blockIdx.x & 31;       // 0..31
    const size_t base = (size_t)e * MTOT + (size_t)b * NTOK;
    float4* p = (float4*)(qkv + base);
    const int tid = threadIdx.x;

    float ss = 0.f;
    for (int i = tid; i < NTOK/4; i += 256) {
        float4 v = p[i];
        ss += v.x*v.x + v.y*v.y + v.z*v.z + v.w*v.w;
    }
#pragma unroll
    for (int o = 16; o > 0; o >>= 1) ss += __shfl_down_sync(0xffffffffu, ss, o);
    __shared__ float red[8];
    if ((tid & 31) == 0) red[tid >> 5] = ss;
    __syncthreads();
    __shared__ float s_inv;
    if (tid == 0) {
        float tot = 0.f;
#pragma unroll
        for (int i = 0; i < 8; i++) tot += red[i];
        s_inv = 1.f / fmaxf(sqrtf(tot), 1e-12f);
    }
    __syncthreads();
    const float inv = s_inv;
    for (int i = tid; i < NTOK/4; i += 256) {
        float4 v = p[i];
        v.x *= inv; v.y *= inv; v.z *= inv; v.w *= inv;
        p[i] = v;
    }
}

// ---------------------------------------------------------------------------
// Fused XCA core per (b, h): S = q k^T * temp -> softmax rows -> out = S v
// q,k,v rows are [48][NTOK] contiguous slices of g_qkv. 256 threads.
// ---------------------------------------------------------------------------
#define NT  128
#define NTP 132
__global__ void __launch_bounds__(256) attn_kernel(
    const float* __restrict__ qkv, const float* __restrict__ temperature,
    float* __restrict__ outp)
{
    extern __shared__ float sm[];
    float* qs = sm;                 // [48][NTP]
    float* ks = sm + 48 * NTP;      // [48][NTP]
    float* attn_s = sm;             // [48][52]   (phase B, aliases qs)
    float* vs = sm + 48 * 52;       // [48][NTP]  (phase B)

    const int bh = blockIdx.x;
    const int b = bh >> 3, h = bh & 7;
    const int tid = threadIdx.x;
    const int tx = tid & 15, ty = tid >> 4;

    const size_t M = (size_t)MTOT;
    const float* qb = qkv + ((size_t)(h * CH)) * M + (size_t)b * NTOK;
    const float* kb = qb + (size_t)DIM * M;
    const float* vb = qb + (size_t)(2 * DIM) * M;
    float* ob = outp + ((size_t)(h * CH)) * M + (size_t)b * NTOK;

    // ---- Phase A: S = q k^T ----
    float acc[3][3];
#pragma unroll
    for (int i = 0; i < 3; i++)
#pragma unroll
        for (int j = 0; j < 3; j++) acc[i][j] = 0.f;

    for (int n0 = 0; n0 < NTOK; n0 += NT) {
        const int lim = min(NT, NTOK - n0);
        for (int idx = tid; idx < CH * NT; idx += 256) {
            int row = idx / NT, col = idx - row * NT;
            float qv = 0.f, kv = 0.f;
            if (col < lim) {
                qv = qb[(size_t)row * M + n0 + col];
                kv = kb[(size_t)row * M + n0 + col];
            }
            qs[row * NTP + col] = qv;
            ks[row * NTP + col] = kv;
        }
        __syncthreads();
#pragma unroll 4
        for (int kk = 0; kk < NT/4; kk++) {
            float4 aq[3], bk[3];
#pragma unroll
            for (int i = 0; i < 3; i++) aq[i] = *(float4*)&qs[(ty*3 + i) * NTP + kk*4];
#pragma unroll
            for (int j = 0; j < 3; j++) bk[j] = *(float4*)&ks[(tx*3 + j) * NTP + kk*4];
#pragma unroll
            for (int i = 0; i < 3; i++)
#pragma unroll
                for (int j = 0; j < 3; j++) {
                    acc[i][j] += aq[i].x * bk[j].x;
                    acc[i][j] += aq[i].y * bk[j].y;
                    acc[i][j] += aq[i].z * bk[j].z;
                    acc[i][j] += aq[i].w * bk[j].w;
                }
        }
        __syncthreads();
    }

    // ---- temperature + stage S to smem ----
    const float temp = temperature[h];
#pragma unroll
    for (int i = 0; i < 3; i++)
#pragma unroll
        for (int j = 0; j < 3; j++)
            attn_s[(ty*3 + i) * 52 + tx*3 + j] = acc[i][j] * temp;
    __syncthreads();

    // ---- softmax over rows (48 rows of 48) ----
    if (tid < CH) {
        float* row = attn_s + tid * 52;
        float mx = -1e30f;
#pragma unroll
        for (int d = 0; d < CH; d++) mx = fmaxf(mx, row[d]);
        float s = 0.f;
#pragma unroll
        for (int d = 0; d < CH; d++) { float e = expf(row[d] - mx); row[d] = e; s += e; }
        float inv = 1.f / s;
#pragma unroll
        for (int d = 0; d < CH; d++) row[d] *= inv;
    }
    __syncthreads();

    // ---- Phase B: out = S v ----
    for (int n0 = 0; n0 < NTOK; n0 += NT) {
        const int lim = min(NT, NTOK - n0);
        for (int idx = tid; idx < CH * NT; idx += 256) {
            int row = idx / NT, col = idx - row * NT;
            vs[row * NTP + col] = (col < lim) ? vb[(size_t)row * M + n0 + col] : 0.f;
        }
        __syncthreads();
        float oacc[3][8];
#pragma unroll
        for (int i = 0; i < 3; i++)
#pragma unroll
            for (int j = 0; j < 8; j++) oacc[i][j] = 0.f;
#pragma unroll 4
        for (int d = 0; d < CH; d++) {
            float a[3];
#pragma unroll
            for (int i = 0; i < 3; i++) a[i] = attn_s[(ty*3 + i) * 52 + d];
            float4 v0 = *(float4*)&vs[d * NTP + tx*8];
            float4 v1 = *(float4*)&vs[d * NTP + tx*8 + 4];
#pragma unroll
            for (int i = 0; i < 3; i++) {
                oacc[i][0] += a[i] * v0.x; oacc[i][1] += a[i] * v0.y;
                oacc[i][2] += a[i] * v0.z; oacc[i][3] += a[i] * v0.w;
                oacc[i][4] += a[i] * v1.x; oacc[i][5] += a[i] * v1.y;
                oacc[i][6] += a[i] * v1.z; oacc[i][7] += a[i] * v1.w;
            }
        }
        if (tx * 8 < lim) {
#pragma unroll
            for (int i = 0; i < 3; i++) {
                size_t off = (size_t)(ty*3 + i) * M + n0 + tx*8;
                float4 v0 = make_float4(oacc[i][0], oacc[i][1], oacc[i][2], oacc[i][3]);
                float4 v1 = make_float4(oacc[i][4], oacc[i][5], oacc[i][6], oacc[i][7]);
                *(float4*)(ob + off)     = v0;
                *(float4*)(ob + off + 4) = v1;
            }
        }
        __syncthreads();
    }
}

// ---------------------------------------------------------------------------
extern "C" void kernel_launch(void* const* d_in, const int* in_sizes, int n_in,
                              void* d_out, int out_size)
{
    const float* x      = (const float*)d_in[0];  // (32, 3136, 384)
    const float* qkv_w  = (const float*)d_in[1];  // (1152, 384)
    const float* temp   = (const float*)d_in[2];  // (8,1,1)
    const float* proj_w = (const float*)d_in[3];  // (384, 384)
    const float* proj_b = (const float*)d_in[4];  // (384,)
    float* out = (float*)d_out;                   // (32, 3136, 384)

    float* qkv_s; float* av_s;
    cudaGetSymbolAddress((void**)&qkv_s, g_qkv);
    cudaGetSymbolAddress((void**)&av_s,  g_av);

    // 1) qkv projection, output transposed: g_qkv[e][m]
    gemm_nt_kernel<<<dim3(MTOT/128, ETOT/128), 256>>>(qkv_w, x, qkv_s, ETOT, MTOT, DIM);

    // 2) L2 normalize q and k over n (per e-row, per batch segment)
    l2norm_kernel<<<dim3(2 * DIM * BATCH), 256>>>(qkv_s);

    // 3) fused XCA: S = q k^T * temp, softmax, out = S v  -> g_av[e'][m]
    const int smem = 2 * CH * NTP * (int)sizeof(float);  // 50688 B
    cudaFuncSetAttribute(attn_kernel, cudaFuncAttributeMaxDynamicSharedMemorySize, smem);
    attn_kernel<<<dim3(BATCH * HEADS), 256, smem>>>(qkv_s, temp, av_s);

    // 4) output projection + bias -> (B, N, D) row-major
    gemm_tn_kernel<<<dim3(MTOT/128, DIM/128), 256>>>(av_s, proj_w, proj_b, out, MTOT, DIM, DIM);
}

// round 5
// speedup vs baseline: 1.3268x; 1.3268x over previous
#include <cuda_runtime.h>
#include <cuda_bf16.h>
#include <math.h>
#include <cstdint>

// Problem constants
#define BATCH 32
#define NTOK  3136
#define DIM   384
#define HEADS 8
#define CH    48
#define MTOT  (BATCH * NTOK)   // 100352
#define ETOT  (3 * DIM)        // 1152
#define KDIM  384

// Scratch
__device__ float g_qkv[(size_t)ETOT * MTOT];   // [e][m]
__device__ float g_av [(size_t)MTOT * DIM];    // [m][e'] (row-major, K-contig for proj GEMM)

__device__ __forceinline__ float tf32r(float x) {
    float r; asm("cvt.rna.tf32.f32 %0, %1;" : "=f"(r) : "f"(x)); return r;
}

#define MMA_TF32(d, A0, A1, A2, A3, B0, B1) \
    asm volatile("mma.sync.aligned.m16n8k8.row.col.f32.tf32.tf32.f32 " \
        "{%0,%1,%2,%3}, {%4,%5,%6,%7}, {%8,%9}, {%0,%1,%2,%3};" \
        : "+f"((d)[0]), "+f"((d)[1]), "+f"((d)[2]), "+f"((d)[3]) \
        : "r"(A0), "r"(A1), "r"(A2), "r"(A3), "r"(B0), "r"(B1))

// ---------------------------------------------------------------------------
// 3xTF32 mma.sync GEMM (NT): C[a][b] = sum_k A[a][k]*B[b][k] (+bias[b])
// A: [rowsA][K] K-contig, B: [rowsB][K] K-contig. Tile 128x128, K-chunk 32.
// 256 threads = 8 warps in 2(m) x 4(n); warp tile 64x32; mma m16n8k8.
// ---------------------------------------------------------------------------
#define TSTRIDE 36                      // floats per smem row (pad vs bank conflicts)
#define TILE_F  (128 * TSTRIDE)         // floats per tile buffer
#define GEMM_SMEM (4 * TILE_F * 4)      // AH, AL, BH, BL  (73728 B)

__global__ void __launch_bounds__(256, 2) gemm_mma_kernel(
    const float* __restrict__ A, const float* __restrict__ B,
    const float* __restrict__ bias, float* __restrict__ C,
    int K, size_t ldc)
{
    extern __shared__ float smem[];
    float* AH = smem;
    float* AL = smem + TILE_F;
    float* BH = smem + 2 * TILE_F;
    float* BL = smem + 3 * TILE_F;

    const int tid  = threadIdx.x;
    const int wid  = tid >> 5;
    const int lane = tid & 31;
    const int g    = lane >> 2;   // group (row within fragment)
    const int t    = lane & 3;    // thread-in-group (col within fragment)
    const int a0 = blockIdx.y * 128;
    const int b0 = blockIdx.x * 128;
    const int wm = (wid >> 2) * 64;   // warp m offset in tile
    const int wn = (wid & 3)  * 32;   // warp n offset in tile

    float acc[4][4][4];
#pragma unroll
    for (int mt = 0; mt < 4; mt++)
#pragma unroll
        for (int nt = 0; nt < 4; nt++)
#pragma unroll
            for (int i = 0; i < 4; i++) acc[mt][nt][i] = 0.f;

    for (int k0 = 0; k0 < K; k0 += 32) {
        // ---- load + tf32-split A and B tiles (128 rows x 32 floats each) ----
#pragma unroll
        for (int tld = 0; tld < 4; tld++) {
            int idx = tid + tld * 256;          // 0..1023
            int row = idx >> 3, q = idx & 7;
            float4 v = *(const float4*)(A + (size_t)(a0 + row) * K + k0 + q * 4);
            float4 h, l;
            h.x = tf32r(v.x); l.x = tf32r(v.x - h.x);
            h.y = tf32r(v.y); l.y = tf32r(v.y - h.y);
            h.z = tf32r(v.z); l.z = tf32r(v.z - h.z);
            h.w = tf32r(v.w); l.w = tf32r(v.w - h.w);
            *(float4*)(AH + row * TSTRIDE + q * 4) = h;
            *(float4*)(AL + row * TSTRIDE + q * 4) = l;
        }
#pragma unroll
        for (int tld = 0; tld < 4; tld++) {
            int idx = tid + tld * 256;
            int row = idx >> 3, q = idx & 7;
            float4 v = *(const float4*)(B + (size_t)(b0 + row) * K + k0 + q * 4);
            float4 h, l;
            h.x = tf32r(v.x); l.x = tf32r(v.x - h.x);
            h.y = tf32r(v.y); l.y = tf32r(v.y - h.y);
            h.z = tf32r(v.z); l.z = tf32r(v.z - h.z);
            h.w = tf32r(v.w); l.w = tf32r(v.w - h.w);
            *(float4*)(BH + row * TSTRIDE + q * 4) = h;
            *(float4*)(BL + row * TSTRIDE + q * 4) = l;
        }
        __syncthreads();

        // ---- mma over 4 k-steps of 8 ----
#pragma unroll
        for (int kk = 0; kk < 4; kk++) {
            const int cb = kk * 8 + t;
            uint32_t ah[4][4], al[4][4];
#pragma unroll
            for (int mt = 0; mt < 4; mt++) {
                int r = wm + mt * 16 + g;
                ah[mt][0] = __float_as_uint(AH[r * TSTRIDE + cb]);
                ah[mt][1] = __float_as_uint(AH[(r + 8) * TSTRIDE + cb]);
                ah[mt][2] = __float_as_uint(AH[r * TSTRIDE + cb + 4]);
                ah[mt][3] = __float_as_uint(AH[(r + 8) * TSTRIDE + cb + 4]);
                al[mt][0] = __float_as_uint(AL[r * TSTRIDE + cb]);
                al[mt][1] = __float_as_uint(AL[(r + 8) * TSTRIDE + cb]);
                al[mt][2] = __float_as_uint(AL[r * TSTRIDE + cb + 4]);
                al[mt][3] = __float_as_uint(AL[(r + 8) * TSTRIDE + cb + 4]);
            }
#pragma unroll
            for (int nt = 0; nt < 4; nt++) {
                int c = wn + nt * 8 + g;     // B row (n index)
                uint32_t bh0 = __float_as_uint(BH[c * TSTRIDE + cb]);
                uint32_t bh1 = __float_as_uint(BH[c * TSTRIDE + cb + 4]);
                uint32_t bl0 = __float_as_uint(BL[c * TSTRIDE + cb]);
                uint32_t bl1 = __float_as_uint(BL[c * TSTRIDE + cb + 4]);
#pragma unroll
                for (int mt = 0; mt < 4; mt++) {
                    MMA_TF32(acc[mt][nt], ah[mt][0], ah[mt][1], ah[mt][2], ah[mt][3], bh0, bh1);
                    MMA_TF32(acc[mt][nt], al[mt][0], al[mt][1], al[mt][2], al[mt][3], bh0, bh1);
                    MMA_TF32(acc[mt][nt], ah[mt][0], ah[mt][1], ah[mt][2], ah[mt][3], bl0, bl1);
                }
            }
        }
        __syncthreads();
    }

    // ---- epilogue ----
#pragma unroll
    for (int mt = 0; mt < 4; mt++) {
        int row = a0 + wm + mt * 16 + g;
#pragma unroll
        for (int nt = 0; nt < 4; nt++) {
            int col = b0 + wn + nt * 8 + 2 * t;
            float b0v = 0.f, b1v = 0.f;
            if (bias) { b0v = bias[col]; b1v = bias[col + 1]; }
            float2 v01 = make_float2(acc[mt][nt][0] + b0v, acc[mt][nt][1] + b1v);
            float2 v23 = make_float2(acc[mt][nt][2] + b0v, acc[mt][nt][3] + b1v);
            *(float2*)(C + (size_t)row * ldc + col)       = v01;
            *(float2*)(C + (size_t)(row + 8) * ldc + col) = v23;
        }
    }
}

// ---------------------------------------------------------------------------
// L2 normalize q and k rows over n. One block per (e, b), e in [0, 768).
// ---------------------------------------------------------------------------
__global__ void __launch_bounds__(256) l2norm_kernel(float* __restrict__ qkv)
{
    const int e = blockIdx.x >> 5;
    const int b = blockIdx.x & 31;
    const size_t base = (size_t)e * MTOT + (size_t)b * NTOK;
    float4* p = (float4*)(qkv + base);
    const int tid = threadIdx.x;

    float ss = 0.f;
    for (int i = tid; i < NTOK/4; i += 256) {
        float4 v = p[i];
        ss += v.x*v.x + v.y*v.y + v.z*v.z + v.w*v.w;
    }
#pragma unroll
    for (int o = 16; o > 0; o >>= 1) ss += __shfl_down_sync(0xffffffffu, ss, o);
    __shared__ float red[8];
    if ((tid & 31) == 0) red[tid >> 5] = ss;
    __syncthreads();
    __shared__ float s_inv;
    if (tid == 0) {
        float tot = 0.f;
#pragma unroll
        for (int i = 0; i < 8; i++) tot += red[i];
        s_inv = 1.f / fmaxf(sqrtf(tot), 1e-12f);
    }
    __syncthreads();
    const float inv = s_inv;
    for (int i = tid; i < NTOK/4; i += 256) {
        float4 v = p[i];
        v.x *= inv; v.y *= inv; v.z *= inv; v.w *= inv;
        p[i] = v;
    }
}

// ---------------------------------------------------------------------------
// Fused XCA core per (b, h): S = q k^T * temp -> softmax rows -> out = S v
// Output written TRANSPOSED: av[(b*NTOK+n)*DIM + h*CH + c]
// ---------------------------------------------------------------------------
#define NT  128
#define NTP 132
__global__ void __launch_bounds__(256) attn_kernel(
    const float* __restrict__ qkv, const float* __restrict__ temperature,
    float* __restrict__ av)
{
    extern __shared__ float sm[];
    float* qs = sm;                      // phase A: [48][NTP]
    float* ks = sm + 48 * NTP;           // phase A: [48][NTP]
    float* attn_s = sm;                  // phase B: [48][52]
    float* vs = sm + 48 * 52;            // phase B: [48][NTP]
    float* tr = sm + 48 * 52 + 48 * NTP; // phase B: [128][52]

    const int bh = blockIdx.x;
    const int b = bh >> 3, h = bh & 7;
    const int tid = threadIdx.x;
    const int tx = tid & 15, ty = tid >> 4;

    const size_t M = (size_t)MTOT;
    const float* qb = qkv + ((size_t)(h * CH)) * M + (size_t)b * NTOK;
    const float* kb = qb + (size_t)DIM * M;
    const float* vb = qb + (size_t)(2 * DIM) * M;

    // ---- Phase A: S = q k^T ----
    float acc[3][3];
#pragma unroll
    for (int i = 0; i < 3; i++)
#pragma unroll
        for (int j = 0; j < 3; j++) acc[i][j] = 0.f;

    for (int n0 = 0; n0 < NTOK; n0 += NT) {
        const int lim = min(NT, NTOK - n0);
        for (int idx = tid; idx < CH * NT; idx += 256) {
            int row = idx / NT, col = idx - row * NT;
            float qv = 0.f, kv = 0.f;
            if (col < lim) {
                qv = qb[(size_t)row * M + n0 + col];
                kv = kb[(size_t)row * M + n0 + col];
            }
            qs[row * NTP + col] = qv;
            ks[row * NTP + col] = kv;
        }
        __syncthreads();
#pragma unroll 4
        for (int kk = 0; kk < NT/4; kk++) {
            float4 aq[3], bk[3];
#pragma unroll
            for (int i = 0; i < 3; i++) aq[i] = *(float4*)&qs[(ty*3 + i) * NTP + kk*4];
#pragma unroll
            for (int j = 0; j < 3; j++) bk[j] = *(float4*)&ks[(tx*3 + j) * NTP + kk*4];
#pragma unroll
            for (int i = 0; i < 3; i++)
#pragma unroll
                for (int j = 0; j < 3; j++) {
                    acc[i][j] += aq[i].x * bk[j].x;
                    acc[i][j] += aq[i].y * bk[j].y;
                    acc[i][j] += aq[i].z * bk[j].z;
                    acc[i][j] += aq[i].w * bk[j].w;
                }
        }
        __syncthreads();
    }

    const float temp = temperature[h];
#pragma unroll
    for (int i = 0; i < 3; i++)
#pragma unroll
        for (int j = 0; j < 3; j++)
            attn_s[(ty*3 + i) * 52 + tx*3 + j] = acc[i][j] * temp;
    __syncthreads();

    if (tid < CH) {
        float* row = attn_s + tid * 52;
        float mx = -1e30f;
#pragma unroll
        for (int d = 0; d < CH; d++) mx = fmaxf(mx, row[d]);
        float s = 0.f;
#pragma unroll
        for (int d = 0; d < CH; d++) { float e = expf(row[d] - mx); row[d] = e; s += e; }
        float inv = 1.f / s;
#pragma unroll
        for (int d = 0; d < CH; d++) row[d] *= inv;
    }
    __syncthreads();

    // ---- Phase B: out = S v, written transposed [n][c] ----
    for (int n0 = 0; n0 < NTOK; n0 += NT) {
        const int lim = min(NT, NTOK - n0);
        for (int idx = tid; idx < CH * NT; idx += 256) {
            int row = idx / NT, col = idx - row * NT;
            vs[row * NTP + col] = (col < lim) ? vb[(size_t)row * M + n0 + col] : 0.f;
        }
        __syncthreads();
        float oacc[3][8];
#pragma unroll
        for (int i = 0; i < 3; i++)
#pragma unroll
            for (int j = 0; j < 8; j++) oacc[i][j] = 0.f;
#pragma unroll 4
        for (int d = 0; d < CH; d++) {
            float a[3];
#pragma unroll
            for (int i = 0; i < 3; i++) a[i] = attn_s[(ty*3 + i) * 52 + d];
            float4 v0 = *(float4*)&vs[d * NTP + tx*8];
            float4 v1 = *(float4*)&vs[d * NTP + tx*8 + 4];
#pragma unroll
            for (int i = 0; i < 3; i++) {
                oacc[i][0] += a[i] * v0.x; oacc[i][1] += a[i] * v0.y;
                oacc[i][2] += a[i] * v0.z; oacc[i][3] += a[i] * v0.w;
                oacc[i][4] += a[i] * v1.x; oacc[i][5] += a[i] * v1.y;
                oacc[i][6] += a[i] * v1.z; oacc[i][7] += a[i] * v1.w;
            }
        }
        // stage transpose: tr[n][c]
#pragma unroll
        for (int i = 0; i < 3; i++)
#pragma unroll
            for (int j = 0; j < 8; j++)
                tr[(tx*8 + j) * 52 + ty*3 + i] = oacc[i][j];
        __syncthreads();
        {
            int row = tid >> 1;
            int half = tid & 1;
            if (row < lim) {
                float* dst = av + ((size_t)(b * NTOK + n0 + row)) * DIM + h * CH + half * 24;
                float* src = tr + row * 52 + half * 24;
#pragma unroll
                for (int t = 0; t < 6; t++)
                    *(float4*)(dst + t * 4) = *(float4*)(src + t * 4);
            }
        }
        __syncthreads();
    }
}

// ---------------------------------------------------------------------------
extern "C" void kernel_launch(void* const* d_in, const int* in_sizes, int n_in,
                              void* d_out, int out_size)
{
    const float* x      = (const float*)d_in[0];  // (32, 3136, 384)
    const float* qkv_w  = (const float*)d_in[1];  // (1152, 384)
    const float* temp   = (const float*)d_in[2];  // (8,1,1)
    const float* proj_w = (const float*)d_in[3];  // (384, 384)
    const float* proj_b = (const float*)d_in[4];  // (384,)
    float* out = (float*)d_out;                   // (32, 3136, 384)

    float* qkv_s; float* av_s;
    cudaGetSymbolAddress((void**)&qkv_s, g_qkv);
    cudaGetSymbolAddress((void**)&av_s,  g_av);

    cudaFuncSetAttribute(gemm_mma_kernel, cudaFuncAttributeMaxDynamicSharedMemorySize, GEMM_SMEM);

    // 1) qkv projection -> g_qkv[e][m]  (a = e rows of qkv_w, b = m rows of x)
    gemm_mma_kernel<<<dim3(MTOT/128, ETOT/128), 256, GEMM_SMEM>>>(
        qkv_w, x, nullptr, qkv_s, KDIM, (size_t)MTOT);

    // 2) L2 normalize q and k over n
    l2norm_kernel<<<dim3(2 * DIM * BATCH), 256>>>(qkv_s);

    // 3) fused XCA -> g_av[m][e']  (transposed output)
    const int asmem = (48 * 52 + 48 * NTP + 128 * 52) * (int)sizeof(float);  // 61952
    cudaFuncSetAttribute(attn_kernel, cudaFuncAttributeMaxDynamicSharedMemorySize, asmem);
    attn_kernel<<<dim3(BATCH * HEADS), 256, asmem>>>(qkv_s, temp, av_s);

    // 4) output projection + bias -> (B, N, D)  (a = m rows of av, b = f rows of proj_w)
    gemm_mma_kernel<<<dim3(DIM/128, MTOT/128), 256, GEMM_SMEM>>>(
        av_s, proj_w, proj_b, out, KDIM, (size_t)DIM);
}

// round 7
// speedup vs baseline: 1.7084x; 1.2876x over previous
#include <cuda_runtime.h>
#include <cuda_bf16.h>
#include <math.h>
#include <cstdint>

// Problem constants
#define BATCH 32
#define NTOK  3136
#define DIM   384
#define HEADS 8
#define CH    48
#define MTOT  (BATCH * NTOK)   // 100352
#define ETOT  (3 * DIM)        // 1152
#define KDIM  384

// Scratch
__device__ float g_qkv[(size_t)ETOT * MTOT];          // [e][m]
__device__ float g_w  [(size_t)BATCH * DIM * DIM];    // per-batch combined P·S weights [b][f][d']

// ---------------------------------------------------------------------------
#define MMA_BF16(d, A0,A1,A2,A3, B0,B1) \
    asm volatile("mma.sync.aligned.m16n8k16.row.col.f32.bf16.bf16.f32 " \
        "{%0,%1,%2,%3}, {%4,%5,%6,%7}, {%8,%9}, {%0,%1,%2,%3};" \
        : "+f"((d)[0]), "+f"((d)[1]), "+f"((d)[2]), "+f"((d)[3]) \
        : "r"(A0), "r"(A1), "r"(A2), "r"(A3), "r"(B0), "r"(B1))

__device__ __forceinline__ void bsplit2(float x0, float x1, uint32_t& h, uint32_t& l) {
    __nv_bfloat16 h0 = __float2bfloat16(x0);
    __nv_bfloat16 h1 = __float2bfloat16(x1);
    __nv_bfloat16 l0 = __float2bfloat16(x0 - __bfloat162float(h0));
    __nv_bfloat16 l1 = __float2bfloat16(x1 - __bfloat162float(h1));
    __nv_bfloat162 hv = __halves2bfloat162(h0, h1);
    __nv_bfloat162 lv = __halves2bfloat162(l0, l1);
    h = *reinterpret_cast<uint32_t*>(&hv);
    l = *reinterpret_cast<uint32_t*>(&lv);
}
__device__ __forceinline__ void bsplit1(float x, __nv_bfloat16& h, __nv_bfloat16& l) {
    h = __float2bfloat16(x);
    l = __float2bfloat16(x - __bfloat162float(h));
}

#define BST   40                       // halves per smem row (conflict-free frag loads)
#define TBUF  (128 * BST)              // halves per tile buffer
#define GSMEM (4 * TBUF * 2)           // bytes: AH, AL, BH, BL = 40960

// ---------------------------------------------------------------------------
// G1: qkv GEMM (NT, both K-contig): C[a][m] = sum_k A[a][k] * B[m][k]
// A = qkv_w [1152][384], B = x [100352][384], C = g_qkv, ldc = MTOT.
// 3xBF16 split, m16n8k16, tile 128x128, K-chunk 32, hoisted-LDG pipeline.
// ---------------------------------------------------------------------------
__global__ void __launch_bounds__(256, 2) gemm_qkv_kernel(
    const float* __restrict__ A, const float* __restrict__ B,
    float* __restrict__ C, int K, size_t ldc)
{
    extern __shared__ __nv_bfloat16 sb[];
    __nv_bfloat16* AH = sb;
    __nv_bfloat16* AL = sb + TBUF;
    __nv_bfloat16* BH = sb + 2 * TBUF;
    __nv_bfloat16* BL = sb + 3 * TBUF;

    const int tid  = threadIdx.x;
    const int wid  = tid >> 5;
    const int lane = tid & 31;
    const int g    = lane >> 2;
    const int t    = lane & 3;
    const int a0 = blockIdx.y * 128;
    const int b0 = blockIdx.x * 128;
    const int wm = (wid >> 2) * 64;
    const int wn = (wid & 3)  * 32;
    const int q  = tid & 7;        // float4 slot (cols 4q..4q+3)
    const int r0 = tid >> 3;       // base row (rows r0 + 32*T)

    float acc[4][4][4];
#pragma unroll
    for (int mt = 0; mt < 4; mt++)
#pragma unroll
        for (int nt = 0; nt < 4; nt++)
#pragma unroll
            for (int i = 0; i < 4; i++) acc[mt][nt][i] = 0.f;

    const int nchunks = K / 32;
    float4 va[4], vb[4];
    // prologue loads (chunk 0)
#pragma unroll
    for (int T = 0; T < 4; T++) {
        va[T] = *(const float4*)(A + (size_t)(a0 + r0 + 32*T) * K + 4*q);
        vb[T] = *(const float4*)(B + (size_t)(b0 + r0 + 32*T) * K + 4*q);
    }

    for (int c = 0; c < nchunks; c++) {
        // convert + store current regs
#pragma unroll
        for (int T = 0; T < 4; T++) {
            int row = r0 + 32*T;
            uint32_t h0, l0, h1, l1;
            bsplit2(va[T].x, va[T].y, h0, l0);
            bsplit2(va[T].z, va[T].w, h1, l1);
            *(uint32_t*)&AH[row*BST + 4*q]     = h0;
            *(uint32_t*)&AH[row*BST + 4*q + 2] = h1;
            *(uint32_t*)&AL[row*BST + 4*q]     = l0;
            *(uint32_t*)&AL[row*BST + 4*q + 2] = l1;
            bsplit2(vb[T].x, vb[T].y, h0, l0);
            bsplit2(vb[T].z, vb[T].w, h1, l1);
            *(uint32_t*)&BH[row*BST + 4*q]     = h0;
            *(uint32_t*)&BH[row*BST + 4*q + 2] = h1;
            *(uint32_t*)&BL[row*BST + 4*q]     = l0;
            *(uint32_t*)&BL[row*BST + 4*q + 2] = l1;
        }
        __syncthreads();
        // hoist next chunk's global loads (in flight during mma)
        if (c + 1 < nchunks) {
            int k0 = (c + 1) * 32;
#pragma unroll
            for (int T = 0; T < 4; T++) {
                va[T] = *(const float4*)(A + (size_t)(a0 + r0 + 32*T) * K + k0 + 4*q);
                vb[T] = *(const float4*)(B + (size_t)(b0 + r0 + 32*T) * K + k0 + 4*q);
            }
        }
        // mma over 2 k-steps of 16
#pragma unroll
        for (int kk = 0; kk < 32; kk += 16) {
            uint32_t bh0[4], bh1[4], bl0[4], bl1[4];
#pragma unroll
            for (int nt = 0; nt < 4; nt++) {
                int cc = wn + nt * 8 + g;
                const __nv_bfloat16* ph = BH + cc*BST + kk + 2*t;
                const __nv_bfloat16* pl = BL + cc*BST + kk + 2*t;
                bh0[nt] = *(const uint32_t*)ph;
                bh1[nt] = *(const uint32_t*)(ph + 8);
                bl0[nt] = *(const uint32_t*)pl;
                bl1[nt] = *(const uint32_t*)(pl + 8);
            }
#pragma unroll
            for (int mt = 0; mt < 4; mt++) {
                int r = wm + mt * 16 + g;
                const __nv_bfloat16* pa = AH + r*BST + kk + 2*t;
                const __nv_bfloat16* pb = AH + (r+8)*BST + kk + 2*t;
                uint32_t ah0 = *(const uint32_t*)pa, ah1 = *(const uint32_t*)pb;
                uint32_t ah2 = *(const uint32_t*)(pa + 8), ah3 = *(const uint32_t*)(pb + 8);
                const __nv_bfloat16* qa = AL + r*BST + kk + 2*t;
                const __nv_bfloat16* qb2 = AL + (r+8)*BST + kk + 2*t;
                uint32_t al0 = *(const uint32_t*)qa, al1 = *(const uint32_t*)qb2;
                uint32_t al2 = *(const uint32_t*)(qa + 8), al3 = *(const uint32_t*)(qb2 + 8);
#pragma unroll
                for (int nt = 0; nt < 4; nt++) {
                    MMA_BF16(acc[mt][nt], ah0, ah1, ah2, ah3, bh0[nt], bh1[nt]);
                    MMA_BF16(acc[mt][nt], al0, al1, al2, al3, bh0[nt], bh1[nt]);
                    MMA_BF16(acc[mt][nt], ah0, ah1, ah2, ah3, bl0[nt], bl1[nt]);
                }
            }
        }
        __syncthreads();
    }

#pragma unroll
    for (int mt = 0; mt < 4; mt++) {
        int row = a0 + wm + mt * 16 + g;
#pragma unroll
        for (int nt = 0; nt < 4; nt++) {
            int col = b0 + wn + nt * 8 + 2 * t;
            *(float2*)(C + (size_t)row * ldc + col)       = make_float2(acc[mt][nt][0], acc[mt][nt][1]);
            *(float2*)(C + (size_t)(row + 8) * ldc + col) = make_float2(acc[mt][nt][2], acc[mt][nt][3]);
        }
    }
}

// ---------------------------------------------------------------------------
// G2: proj GEMM per batch: out[b,n,f] = sum_d' W_b[f][d'] * v[d'][b,n] + bias[f]
// A-operand (m-frag) = v tile [n=128][k=32] (transpose-loaded from [k][n] gmem),
// B-operand (n-frag) = W_b [f][k] K-contig. grid (3 f-tiles, 25 n-tiles, 32 b).
// ---------------------------------------------------------------------------
__global__ void __launch_bounds__(256, 2) gemm_proj_kernel(
    const float* __restrict__ qkv, const float* __restrict__ W,
    const float* __restrict__ bias, float* __restrict__ out)
{
    extern __shared__ __nv_bfloat16 sb[];
    __nv_bfloat16* AH = sb;
    __nv_bfloat16* AL = sb + TBUF;
    __nv_bfloat16* BH = sb + 2 * TBUF;
    __nv_bfloat16* BL = sb + 3 * TBUF;

    const int tid  = threadIdx.x;
    const int wid  = tid >> 5;
    const int lane = tid & 31;
    const int g    = lane >> 2;
    const int t    = lane & 3;
    const int f0 = blockIdx.x * 128;
    const int n0 = blockIdx.y * 128;
    const int b  = blockIdx.z;
    const int wm = (wid >> 2) * 64;
    const int wn = (wid & 3)  * 32;
    // v (A) load coords: rows k, cols n
    const int c4  = tid & 31;        // float4 col slot (n = 4*c4..)
    const int kr0 = tid >> 5;        // base k row (rows kr0 + 8*T)
    // W (B) load coords
    const int q  = tid & 7;
    const int r0 = tid >> 3;

    const float* vbase = qkv + (size_t)(2 * DIM) * MTOT + (size_t)b * NTOK;
    const float* Wb    = W + (size_t)b * DIM * DIM;
    const int nlim = NTOK - n0;      // valid n count in this tile (128 or 64)

    float acc[4][4][4];
#pragma unroll
    for (int mt = 0; mt < 4; mt++)
#pragma unroll
        for (int nt = 0; nt < 4; nt++)
#pragma unroll
            for (int i = 0; i < 4; i++) acc[mt][nt][i] = 0.f;

    const int nchunks = KDIM / 32;
    float4 va[4], vb4[4];
#pragma unroll
    for (int T = 0; T < 4; T++) {
        va[T] = (4*c4 < nlim)
              ? *(const float4*)(vbase + (size_t)(kr0 + 8*T) * MTOT + n0 + 4*c4)
              : make_float4(0.f, 0.f, 0.f, 0.f);
        vb4[T] = *(const float4*)(Wb + (size_t)(f0 + r0 + 32*T) * KDIM + 4*q);
    }

    for (int c = 0; c < nchunks; c++) {
        // store v transposed: smem [n][k]
#pragma unroll
        for (int T = 0; T < 4; T++) {
            int krow = kr0 + 8*T;
            float xv[4] = {va[T].x, va[T].y, va[T].z, va[T].w};
#pragma unroll
            for (int j = 0; j < 4; j++) {
                __nv_bfloat16 h, l;
                bsplit1(xv[j], h, l);
                AH[(4*c4 + j)*BST + krow] = h;
                AL[(4*c4 + j)*BST + krow] = l;
            }
            int row = r0 + 32*T;
            uint32_t h0, l0, h1, l1;
            bsplit2(vb4[T].x, vb4[T].y, h0, l0);
            bsplit2(vb4[T].z, vb4[T].w, h1, l1);
            *(uint32_t*)&BH[row*BST + 4*q]     = h0;
            *(uint32_t*)&BH[row*BST + 4*q + 2] = h1;
            *(uint32_t*)&BL[row*BST + 4*q]     = l0;
            *(uint32_t*)&BL[row*BST + 4*q + 2] = l1;
        }
        __syncthreads();
        if (c + 1 < nchunks) {
            int k0 = (c + 1) * 32;
#pragma unroll
            for (int T = 0; T < 4; T++) {
                va[T] = (4*c4 < nlim)
                      ? *(const float4*)(vbase + (size_t)(k0 + kr0 + 8*T) * MTOT + n0 + 4*c4)
                      : make_float4(0.f, 0.f, 0.f, 0.f);
                vb4[T] = *(const float4*)(Wb + (size_t)(f0 + r0 + 32*T) * KDIM + k0 + 4*q);
            }
        }
#pragma unroll
        for (int kk = 0; kk < 32; kk += 16) {
            uint32_t bh0[4], bh1[4], bl0[4], bl1[4];
#pragma unroll
            for (int nt = 0; nt < 4; nt++) {
                int cc = wn + nt * 8 + g;
                const __nv_bfloat16* ph = BH + cc*BST + kk + 2*t;
                const __nv_bfloat16* pl = BL + cc*BST + kk + 2*t;
                bh0[nt] = *(const uint32_t*)ph;
                bh1[nt] = *(const uint32_t*)(ph + 8);
                bl0[nt] = *(const uint32_t*)pl;
                bl1[nt] = *(const uint32_t*)(pl + 8);
            }
#pragma unroll
            for (int mt = 0; mt < 4; mt++) {
                int r = wm + mt * 16 + g;
                const __nv_bfloat16* pa = AH + r*BST + kk + 2*t;
                const __nv_bfloat16* pb = AH + (r+8)*BST + kk + 2*t;
                uint32_t ah0 = *(const uint32_t*)pa, ah1 = *(const uint32_t*)pb;
                uint32_t ah2 = *(const uint32_t*)(pa + 8), ah3 = *(const uint32_t*)(pb + 8);
                const __nv_bfloat16* qa = AL + r*BST + kk + 2*t;
                const __nv_bfloat16* qb2 = AL + (r+8)*BST + kk + 2*t;
                uint32_t al0 = *(const uint32_t*)qa, al1 = *(const uint32_t*)qb2;
                uint32_t al2 = *(const uint32_t*)(qa + 8), al3 = *(const uint32_t*)(qb2 + 8);
#pragma unroll
                for (int nt = 0; nt < 4; nt++) {
                    MMA_BF16(acc[mt][nt], ah0, ah1, ah2, ah3, bh0[nt], bh1[nt]);
                    MMA_BF16(acc[mt][nt], al0, al1, al2, al3, bh0[nt], bh1[nt]);
                    MMA_BF16(acc[mt][nt], ah0, ah1, ah2, ah3, bl0[nt], bl1[nt]);
                }
            }
        }
        __syncthreads();
    }

    // epilogue: C[n][f] with bias
#pragma unroll
    for (int mt = 0; mt < 4; mt++) {
        int nrow = wm + mt * 16 + g;   // n within tile
#pragma unroll
        for (int nt = 0; nt < 4; nt++) {
            int col = f0 + wn + nt * 8 + 2 * t;
            float bv0 = bias[col], bv1 = bias[col + 1];
            if (nrow < nlim)
                *(float2*)(out + ((size_t)b * NTOK + n0 + nrow) * DIM + col) =
                    make_float2(acc[mt][nt][0] + bv0, acc[mt][nt][1] + bv1);
            if (nrow + 8 < nlim)
                *(float2*)(out + ((size_t)b * NTOK + n0 + nrow + 8) * DIM + col) =
                    make_float2(acc[mt][nt][2] + bv0, acc[mt][nt][3] + bv1);
        }
    }
}

// ---------------------------------------------------------------------------
// S-kernel per (b,h): raw QK^T + row norms (normalization folded) -> softmax
// -> W_b head-block = P_head · S  written to g_w[b][f][h*48+d].
// ---------------------------------------------------------------------------
#define NT  128
#define NTP 132
__global__ void __launch_bounds__(256) attn_s_kernel(
    const float* __restrict__ qkv, const float* __restrict__ temperature,
    const float* __restrict__ projw, float* __restrict__ gw)
{
    extern __shared__ float sm[];
    float* qs = sm;                      // [48][NTP]
    float* ks = sm + 48 * NTP;           // [48][NTP]
    float* norms = sm + 96 * NTP;        // [96] inverse norms (q:0-47, k:48-95)
    float* attn_s = sm;                  // aliases qs after phase A: [48][52]

    const int bh = blockIdx.x;
    const int b = bh >> 3, h = bh & 7;
    const int tid = threadIdx.x;
    const int tx = tid & 15, ty = tid >> 4;

    const size_t M = (size_t)MTOT;
    const float* qb = qkv + ((size_t)(h * CH)) * M + (size_t)b * NTOK;
    const float* kb = qb + (size_t)DIM * M;

    float acc[3][3];
#pragma unroll
    for (int i = 0; i < 3; i++)
#pragma unroll
        for (int j = 0; j < 3; j++) acc[i][j] = 0.f;
    float nacc = 0.f;

    for (int n0 = 0; n0 < NTOK; n0 += NT) {
        const int lim = min(NT, NTOK - n0);
        for (int idx = tid; idx < CH * NT; idx += 256) {
            int row = idx / NT, col = idx - row * NT;
            float qv = 0.f, kv = 0.f;
            if (col < lim) {
                qv = qb[(size_t)row * M + n0 + col];
                kv = kb[(size_t)row * M + n0 + col];
            }
            qs[row * NTP + col] = qv;
            ks[row * NTP + col] = kv;
        }
        __syncthreads();
        // norm accumulation (threads 0..95, one row each)
        if (tid < 96) {
            const float* src = (tid < 48) ? (qs + tid * NTP) : (ks + (tid - 48) * NTP);
#pragma unroll 4
            for (int i = 0; i < NT / 4; i++) {
                float4 v = *(const float4*)(src + 4 * i);
                nacc += v.x*v.x + v.y*v.y + v.z*v.z + v.w*v.w;
            }
        }
#pragma unroll 4
        for (int kk = 0; kk < NT / 4; kk++) {
            float4 aq[3], bk[3];
#pragma unroll
            for (int i = 0; i < 3; i++) aq[i] = *(float4*)&qs[(ty*3 + i) * NTP + kk*4];
#pragma unroll
            for (int j = 0; j < 3; j++) bk[j] = *(float4*)&ks[(tx*3 + j) * NTP + kk*4];
#pragma unroll
            for (int i = 0; i < 3; i++)
#pragma unroll
                for (int j = 0; j < 3; j++) {
                    acc[i][j] += aq[i].x * bk[j].x;
                    acc[i][j] += aq[i].y * bk[j].y;
                    acc[i][j] += aq[i].z * bk[j].z;
                    acc[i][j] += aq[i].w * bk[j].w;
                }
        }
        __syncthreads();
    }

    if (tid < 96) norms[tid] = 1.f / fmaxf(sqrtf(nacc), 1e-12f);
    __syncthreads();

    // stage scaled dots: S = temp * (q.k)/(|q||k|)
    const float temp = temperature[h];
#pragma unroll
    for (int i = 0; i < 3; i++) {
        float iq = norms[ty*3 + i];
#pragma unroll
        for (int j = 0; j < 3; j++)
            attn_s[(ty*3 + i) * 52 + tx*3 + j] = acc[i][j] * iq * norms[48 + tx*3 + j] * temp;
    }
    __syncthreads();

    if (tid < CH) {
        float* row = attn_s + tid * 52;
        float mx = -1e30f;
#pragma unroll
        for (int d = 0; d < CH; d++) mx = fmaxf(mx, row[d]);
        float s = 0.f;
#pragma unroll
        for (int d = 0; d < CH; d++) { float e = expf(row[d] - mx); row[d] = e; s += e; }
        float inv = 1.f / s;
#pragma unroll
        for (int d = 0; d < CH; d++) row[d] *= inv;
    }
    __syncthreads();

    // W_b head-block: gw[b][f][h*48+d] = sum_c projw[f][h*48+c] * S[c][d]
    const int fl = tid >> 1;              // 0..127
    const int dh = (tid & 1) * 24;        // 0 or 24
    for (int rep = 0; rep < 3; rep++) {
        int f = fl + rep * 128;
        const float* prow = projw + (size_t)f * DIM + h * CH;
        float4 w[6];
#pragma unroll
        for (int j = 0; j < 6; j++) w[j] = make_float4(0.f, 0.f, 0.f, 0.f);
        for (int c = 0; c < CH; c++) {
            float pf = prow[c];
            const float* srow = attn_s + c * 52 + dh;
#pragma unroll
            for (int j = 0; j < 6; j++) {
                float4 s = *(const float4*)(srow + 4 * j);
                w[j].x += pf * s.x; w[j].y += pf * s.y;
                w[j].z += pf * s.z; w[j].w += pf * s.w;
            }
        }
        float* dst = gw + ((size_t)b * DIM + f) * DIM + h * CH + dh;
#pragma unroll
        for (int j = 0; j < 6; j++) *(float4*)(dst + 4 * j) = w[j];
    }
}

// ---------------------------------------------------------------------------
extern "C" void kernel_launch(void* const* d_in, const int* in_sizes, int n_in,
                              void* d_out, int out_size)
{
    const float* x      = (const float*)d_in[0];  // (32, 3136, 384)
    const float* qkv_w  = (const float*)d_in[1];  // (1152, 384)
    const float* temp   = (const float*)d_in[2];  // (8,1,1)
    const float* proj_w = (const float*)d_in[3];  // (384, 384)
    const float* proj_b = (const float*)d_in[4];  // (384,)
    float* out = (float*)d_out;                   // (32, 3136, 384)

    float* qkv_s; float* w_s;
    cudaGetSymbolAddress((void**)&qkv_s, g_qkv);
    cudaGetSymbolAddress((void**)&w_s,  g_w);

    // 1) qkv projection -> g_qkv[e][m]
    gemm_qkv_kernel<<<dim3(MTOT/128, ETOT/128), 256, GSMEM>>>(
        qkv_w, x, qkv_s, KDIM, (size_t)MTOT);

    // 2) S + norms + softmax + P·S combine -> g_w[b][f][d']
    const int asmem = (96 * NTP + 96) * (int)sizeof(float);  // 51072
    cudaFuncSetAttribute(attn_s_kernel, cudaFuncAttributeMaxDynamicSharedMemorySize, asmem);
    attn_s_kernel<<<dim3(BATCH * HEADS), 256, asmem>>>(qkv_s, temp, proj_w, w_s);

    // 3) out = W_b · v + bias  (per batch)
    gemm_proj_kernel<<<dim3(DIM/128, (NTOK + 127)/128, BATCH), 256, GSMEM>>>(
        qkv_s, w_s, proj_b, out);
}

// round 10
// speedup vs baseline: 2.0627x; 1.2074x over previous
#include <cuda_runtime.h>
#include <cuda_bf16.h>
#include <math.h>
#include <cstdint>

#define BATCH 32
#define NTOK  3136
#define DIM   384
#define HEADS 8
#define CH    48
#define MTOT  (BATCH * NTOK)   // 100352
#define ETOT  (3 * DIM)        // 1152
#define KD    384

typedef __nv_bfloat16 bf16;

// Scratch (__device__ globals; no allocs allowed)
__device__ float g_qk [(size_t)(2 * DIM) * MTOT];            // q,k fp32 [e][m]
__device__ bf16  g_xh [(size_t)MTOT * KD];
__device__ bf16  g_xl [(size_t)MTOT * KD];
__device__ bf16  g_wqh[(size_t)ETOT * KD];
__device__ bf16  g_wql[(size_t)ETOT * KD];
__device__ bf16  g_vth[((size_t)MTOT + 128) * KD];           // v^T [m][d] bf16-high
__device__ bf16  g_vtl[((size_t)MTOT + 128) * KD];           // v^T low
__device__ bf16  g_wh [(size_t)BATCH * DIM * DIM];           // W_b = P·S high [b][f][d]
__device__ bf16  g_wl [(size_t)BATCH * DIM * DIM];
__device__ float g_ps [512 * 48 * 48];                       // partial S
__device__ float g_pn [512 * 96];                            // partial sq-norms

// ---------------------------------------------------------------------------
__device__ __forceinline__ uint32_t smem_u32(const void* p) {
    uint32_t a;
    asm("{ .reg .u64 t; cvta.to.shared.u64 t, %1; cvt.u32.u64 %0, t; }" : "=r"(a) : "l"(p));
    return a;
}
__device__ __forceinline__ void bsplit2(float x0, float x1, uint32_t& h, uint32_t& l) {
    __nv_bfloat16 h0 = __float2bfloat16(x0);
    __nv_bfloat16 h1 = __float2bfloat16(x1);
    __nv_bfloat16 l0 = __float2bfloat16(x0 - __bfloat162float(h0));
    __nv_bfloat16 l1 = __float2bfloat16(x1 - __bfloat162float(h1));
    __nv_bfloat162 hv = __halves2bfloat162(h0, h1);
    __nv_bfloat162 lv = __halves2bfloat162(l0, l1);
    h = *reinterpret_cast<uint32_t*>(&hv);
    l = *reinterpret_cast<uint32_t*>(&lv);
}
__device__ __forceinline__ void cp16(uint32_t d, const void* s) {
    asm volatile("cp.async.cg.shared.global [%0], [%1], 16;" :: "r"(d), "l"(s));
}
__device__ __forceinline__ void cp_commit() { asm volatile("cp.async.commit_group;"); }

#define LDSM4(r0, r1, r2, r3, addr) \
    asm volatile("ldmatrix.sync.aligned.m8n8.x4.shared.b16 {%0,%1,%2,%3}, [%4];" \
        : "=r"(r0), "=r"(r1), "=r"(r2), "=r"(r3) : "r"(addr))

#define MMA_BF16(d, A0,A1,A2,A3, B0,B1) \
    asm volatile("mma.sync.aligned.m16n8k16.row.col.f32.bf16.bf16.f32 " \
        "{%0,%1,%2,%3}, {%4,%5,%6,%7}, {%8,%9}, {%0,%1,%2,%3};" \
        : "+f"((d)[0]), "+f"((d)[1]), "+f"((d)[2]), "+f"((d)[3]) \
        : "r"(A0), "r"(A1), "r"(A2), "r"(A3), "r"(B0), "r"(B1))

// ---------------------------------------------------------------------------
// Shared GEMM machinery: tile 128x128, K=384 in 12 chunks of 32.
// smem stage: AH | AL | BH | BL, each 128 rows x 32 halves (stride 40 halves).
// ---------------------------------------------------------------------------
#define BST     40
#define TILE_B  (128 * BST * 2)      // 10240 B per tile
#define STAGE_B (4 * TILE_B)         // 40960 B
#define GSMEM   (2 * STAGE_B)        // 81920 B (double buffer)

__device__ __forceinline__ void load_stage(
    uint32_t sb, const bf16* Ah, const bf16* Al,
    const bf16* Bh, const bf16* Bl, int k0, int tid)
{
    const int row = tid >> 1;
    const int s2  = (tid & 1) * 2;              // 16B seg pair: s2, s2+1 of 4
    const uint32_t ro = row * 80 + s2 * 16;     // bytes within tile
    const size_t go = (size_t)row * KD + k0 + s2 * 8;
    cp16(sb + ro,                Ah + go);  cp16(sb + ro + 16,                Ah + go + 8);
    cp16(sb + TILE_B + ro,       Al + go);  cp16(sb + TILE_B + ro + 16,       Al + go + 8);
    cp16(sb + 2*TILE_B + ro,     Bh + go);  cp16(sb + 2*TILE_B + ro + 16,     Bh + go + 8);
    cp16(sb + 3*TILE_B + ro,     Bl + go);  cp16(sb + 3*TILE_B + ro + 16,     Bl + go + 8);
}

__device__ __forceinline__ void mma_stage(
    uint32_t sb, int wm, int wn, int lane, float acc[4][4][4])
{
    const int j  = lane >> 3;
    const int rr = lane & 7;
#pragma unroll
    for (int kk = 0; kk < 32; kk += 16) {
        uint32_t bh[4][2], bl[4][2];
#pragma unroll
        for (int p = 0; p < 2; p++) {
            uint32_t off = (uint32_t)(((wn + (2*p + (j >> 1)) * 8 + rr) * BST + kk + (j & 1) * 8) * 2);
            LDSM4(bh[2*p][0], bh[2*p][1], bh[2*p+1][0], bh[2*p+1][1], sb + 2*TILE_B + off);
            LDSM4(bl[2*p][0], bl[2*p][1], bl[2*p+1][0], bl[2*p+1][1], sb + 3*TILE_B + off);
        }
#pragma unroll
        for (int mt = 0; mt < 4; mt++) {
            uint32_t aoff = (uint32_t)(((wm + mt*16 + (j & 1) * 8 + rr) * BST + kk + (j >> 1) * 8) * 2);
            uint32_t a0r, a1r, a2r, a3r, l0r, l1r, l2r, l3r;
            LDSM4(a0r, a1r, a2r, a3r, sb + aoff);
            LDSM4(l0r, l1r, l2r, l3r, sb + TILE_B + aoff);
#pragma unroll
            for (int nt = 0; nt < 4; nt++) {
                MMA_BF16(acc[mt][nt], a0r, a1r, a2r, a3r, bh[nt][0], bh[nt][1]);
                MMA_BF16(acc[mt][nt], l0r, l1r, l2r, l3r, bh[nt][0], bh[nt][1]);
                MMA_BF16(acc[mt][nt], a0r, a1r, a2r, a3r, bl[nt][0], bl[nt][1]);
            }
        }
    }
}

__device__ __forceinline__ void gemm_mainloop(
    uint32_t sbase, const bf16* Ah, const bf16* Al,
    const bf16* Bh, const bf16* Bl,
    int wm, int wn, int lane, int tid, float acc[4][4][4])
{
    load_stage(sbase, Ah, Al, Bh, Bl, 0, tid);
    cp_commit();
    for (int c = 0; c < 12; c++) {
        if (c < 11) {
            load_stage(sbase + ((c + 1) & 1) * STAGE_B, Ah, Al, Bh, Bl, (c + 1) * 32, tid);
            cp_commit();
            asm volatile("cp.async.wait_group 1;");
        } else {
            asm volatile("cp.async.wait_group 0;");
        }
        __syncthreads();
        mma_stage(sbase + (c & 1) * STAGE_B, wm, wn, lane, acc);
        __syncthreads();
    }
}

// ---------------------------------------------------------------------------
// Prepass: fp32 -> bf16 h/l split arrays
// ---------------------------------------------------------------------------
__global__ void __launch_bounds__(256) split_kernel(
    const float4* __restrict__ src, uint2* __restrict__ dh, uint2* __restrict__ dl, int n4)
{
    int i = blockIdx.x * 256 + threadIdx.x;
    if (i >= n4) return;
    float4 v = src[i];
    uint32_t h0, l0, h1, l1;
    bsplit2(v.x, v.y, h0, l0);
    bsplit2(v.z, v.w, h1, l1);
    dh[i] = make_uint2(h0, h1);
    dl[i] = make_uint2(l0, l1);
}

// ---------------------------------------------------------------------------
// G1: qkv GEMM. C[e][m]. q/k tiles -> fp32 g_qk; v tiles -> transposed bf16 split.
// ---------------------------------------------------------------------------
__global__ void __launch_bounds__(256, 2) gemm_qkv_kernel()
{
    extern __shared__ char sb[];
    const uint32_t sbase = smem_u32(sb);
    const int tid  = threadIdx.x;
    const int wid  = tid >> 5;
    const int lane = tid & 31;
    const int g = lane >> 2, t = lane & 3;
    const int a0 = blockIdx.y * 128;   // e
    const int b0 = blockIdx.x * 128;   // m
    const int wm = (wid >> 2) * 64, wn = (wid & 3) * 32;

    float acc[4][4][4];
#pragma unroll
    for (int mt = 0; mt < 4; mt++)
#pragma unroll
        for (int nt = 0; nt < 4; nt++)
#pragma unroll
            for (int i = 0; i < 4; i++) acc[mt][nt][i] = 0.f;

    gemm_mainloop(sbase,
                  g_wqh + (size_t)a0 * KD, g_wql + (size_t)a0 * KD,
                  g_xh  + (size_t)b0 * KD, g_xl  + (size_t)b0 * KD,
                  wm, wn, lane, tid, acc);

    if (a0 < 2 * DIM) {
        // q/k: fp32 [e][m]
#pragma unroll
        for (int mt = 0; mt < 4; mt++) {
            int row = a0 + wm + mt * 16 + g;
#pragma unroll
            for (int nt = 0; nt < 4; nt++) {
                int col = b0 + wn + nt * 8 + 2 * t;
                *(float2*)(g_qk + (size_t)row * MTOT + col) =
                    make_float2(acc[mt][nt][0], acc[mt][nt][1]);
                *(float2*)(g_qk + (size_t)(row + 8) * MTOT + col) =
                    make_float2(acc[mt][nt][2], acc[mt][nt][3]);
            }
        }
    } else {
        // v: transpose-stage in smem then bf16 h/l split to g_vth/g_vtl [m][d]
        float* smf = (float*)sb;  // [128 m][132 e]
#pragma unroll
        for (int mt = 0; mt < 4; mt++) {
            int er = wm + mt * 16 + g;
#pragma unroll
            for (int nt = 0; nt < 4; nt++) {
                int mc = wn + nt * 8 + 2 * t;
                smf[mc * 132 + er]             = acc[mt][nt][0];
                smf[(mc + 1) * 132 + er]       = acc[mt][nt][1];
                smf[mc * 132 + er + 8]         = acc[mt][nt][2];
                smf[(mc + 1) * 132 + er + 8]   = acc[mt][nt][3];
            }
        }
        __syncthreads();
        const int mrow = tid >> 1, hf = tid & 1;
        const int dv0 = a0 - 2 * DIM;
        const float* srow = smf + mrow * 132 + hf * 64;
        uint32_t* th = (uint32_t*)(g_vth + (size_t)(b0 + mrow) * KD + dv0 + hf * 64);
        uint32_t* tl = (uint32_t*)(g_vtl + (size_t)(b0 + mrow) * KD + dv0 + hf * 64);
#pragma unroll
        for (int jj = 0; jj < 32; jj++) {
            uint32_t hw, lw;
            bsplit2(srow[2 * jj], srow[2 * jj + 1], hw, lw);
            th[jj] = hw;
            tl[jj] = lw;
        }
    }
}

// ---------------------------------------------------------------------------
// G2: proj GEMM per batch. out[n][f] = sum_d vT[n][d] * W_b[f][d] + bias[f]
// ---------------------------------------------------------------------------
__global__ void __launch_bounds__(256, 2) gemm_proj_kernel(
    const float* __restrict__ bias, float* __restrict__ out)
{
    extern __shared__ char sb[];
    const uint32_t sbase = smem_u32(sb);
    const int tid  = threadIdx.x;
    const int wid  = tid >> 5;
    const int lane = tid & 31;
    const int g = lane >> 2, t = lane & 3;
    const int f0 = blockIdx.x * 128;
    const int n0 = blockIdx.y * 128;
    const int b  = blockIdx.z;
    const int wm = (wid >> 2) * 64, wn = (wid & 3) * 32;
    const size_t vrow0 = (size_t)b * NTOK + n0;
    const size_t wrow0 = (size_t)b * DIM + f0;
    const int nlim = NTOK - n0;

    float acc[4][4][4];
#pragma unroll
    for (int mt = 0; mt < 4; mt++)
#pragma unroll
        for (int nt = 0; nt < 4; nt++)
#pragma unroll
            for (int i = 0; i < 4; i++) acc[mt][nt][i] = 0.f;

    gemm_mainloop(sbase,
                  g_vth + vrow0 * KD, g_vtl + vrow0 * KD,
                  g_wh  + wrow0 * KD, g_wl  + wrow0 * KD,
                  wm, wn, lane, tid, acc);

#pragma unroll
    for (int mt = 0; mt < 4; mt++) {
        int nrow = wm + mt * 16 + g;
#pragma unroll
        for (int nt = 0; nt < 4; nt++) {
            int col = f0 + wn + nt * 8 + 2 * t;
            float bv0 = bias[col], bv1 = bias[col + 1];
            if (nrow < nlim)
                *(float2*)(out + ((size_t)b * NTOK + n0 + nrow) * DIM + col) =
                    make_float2(acc[mt][nt][0] + bv0, acc[mt][nt][1] + bv1);
            if (nrow + 8 < nlim)
                *(float2*)(out + ((size_t)b * NTOK + n0 + nrow + 8) * DIM + col) =
                    make_float2(acc[mt][nt][2] + bv0, acc[mt][nt][3] + bv1);
        }
    }
}

// ---------------------------------------------------------------------------
// attn part: per (b,h,half) partial raw QK^T (48x48) + partial sq-norms (96)
// ---------------------------------------------------------------------------
#define NT  128
#define NTP 132
__global__ void __launch_bounds__(256) attn_part_kernel()
{
    extern __shared__ float sm[];
    float* qs = sm;                // [48][NTP]
    float* ks = sm + 48 * NTP;     // [48][NTP]

    const int blk = blockIdx.x;          // 0..511
    const int bh = blk >> 1, half = blk & 1;
    const int b = bh >> 3, h = bh & 7;
    const int tid = threadIdx.x;
    const int tx = tid & 15, ty = tid >> 4;

    const size_t M = (size_t)MTOT;
    const float* qb = g_qk + ((size_t)(h * CH)) * M + (size_t)b * NTOK;
    const float* kb = qb + (size_t)DIM * M;

    const int nbeg = half * (NTOK / 2);
    const int nend = nbeg + NTOK / 2;

    float acc[3][3];
#pragma unroll
    for (int i = 0; i < 3; i++)
#pragma unroll
        for (int j = 0; j < 3; j++) acc[i][j] = 0.f;
    float nacc = 0.f;

    for (int n0 = nbeg; n0 < nend; n0 += NT) {
        const int lim = min(NT, nend - n0);
        for (int idx = tid; idx < CH * NT; idx += 256) {
            int row = idx / NT, col = idx - row * NT;
            float qv = 0.f, kv = 0.f;
            if (col < lim) {
                qv = qb[(size_t)row * M + n0 + col];
                kv = kb[(size_t)row * M + n0 + col];
            }
            qs[row * NTP + col] = qv;
            ks[row * NTP + col] = kv;
        }
        __syncthreads();
        if (tid < 96) {
            const float* src = (tid < 48) ? (qs + tid * NTP) : (ks + (tid - 48) * NTP);
#pragma unroll 4
            for (int i = 0; i < NT / 4; i++) {
                float4 v = *(const float4*)(src + 4 * i);
                nacc += v.x*v.x + v.y*v.y + v.z*v.z + v.w*v.w;
            }
        }
#pragma unroll 4
        for (int kk = 0; kk < NT / 4; kk++) {
            float4 aq[3], bk[3];
#pragma unroll
            for (int i = 0; i < 3; i++) aq[i] = *(float4*)&qs[(ty*3 + i) * NTP + kk*4];
#pragma unroll
            for (int j = 0; j < 3; j++) bk[j] = *(float4*)&ks[(tx*3 + j) * NTP + kk*4];
#pragma unroll
            for (int i = 0; i < 3; i++)
#pragma unroll
                for (int j = 0; j < 3; j++) {
                    acc[i][j] += aq[i].x * bk[j].x;
                    acc[i][j] += aq[i].y * bk[j].y;
                    acc[i][j] += aq[i].z * bk[j].z;
                    acc[i][j] += aq[i].w * bk[j].w;
                }
        }
        __syncthreads();
    }

    float* ps = g_ps + (size_t)blk * 48 * 48;
#pragma unroll
    for (int i = 0; i < 3; i++)
#pragma unroll
        for (int j = 0; j < 3; j++)
            ps[(ty*3 + i) * 48 + tx*3 + j] = acc[i][j];
    if (tid < 96) g_pn[blk * 96 + tid] = nacc;
}

// ---------------------------------------------------------------------------
// attn combine: sum partials, normalize, temp, softmax, W_b = P·S -> bf16 split
// ---------------------------------------------------------------------------
__global__ void __launch_bounds__(256) attn_combine_kernel(
    const float* __restrict__ temperature, const float* __restrict__ projw)
{
    __shared__ float S[48 * 52];
    __shared__ float norms[96];

    const int bh = blockIdx.x;
    const int b = bh >> 3, h = bh & 7;
    const int tid = threadIdx.x;

    const float* ps0 = g_ps + (size_t)(bh * 2) * 2304;
    const float* ps1 = ps0 + 2304;
    for (int c = tid; c < 2304; c += 256)
        S[(c / 48) * 52 + (c % 48)] = ps0[c] + ps1[c];
    if (tid < 96) {
        float n = g_pn[(bh * 2) * 96 + tid] + g_pn[(bh * 2 + 1) * 96 + tid];
        norms[tid] = 1.f / fmaxf(sqrtf(n), 1e-12f);
    }
    __syncthreads();

    const float temp = temperature[h];
    for (int c = tid; c < 2304; c += 256) {
        int i = c / 48, j = c % 48;
        S[i * 52 + j] *= norms[i] * norms[48 + j] * temp;
    }
    __syncthreads();

    if (tid < CH) {
        float* row = S + tid * 52;
        float mx = -1e30f;
#pragma unroll
        for (int d = 0; d < CH; d++) mx = fmaxf(mx, row[d]);
        float s = 0.f;
#pragma unroll
        for (int d = 0; d < CH; d++) { float e = expf(row[d] - mx); row[d] = e; s += e; }
        float inv = 1.f / s;
#pragma unroll
        for (int d = 0; d < CH; d++) row[d] *= inv;
    }
    __syncthreads();

    // W_b[f][h*48+d] = sum_c projw[f][h*48+c] * S[c][d], split to bf16 h/l
    const int fl = tid >> 1;
    const int dh = (tid & 1) * 24;
    for (int rep = 0; rep < 3; rep++) {
        int f = fl + rep * 128;
        const float* prow = projw + (size_t)f * DIM + h * CH;
        float4 w[6];
#pragma unroll
        for (int j = 0; j < 6; j++) w[j] = make_float4(0.f, 0.f, 0.f, 0.f);
        for (int c = 0; c < CH; c++) {
            float pf = prow[c];
            const float* srow = S + c * 52 + dh;
#pragma unroll
            for (int j = 0; j < 6; j++) {
                float4 s = *(const float4*)(srow + 4 * j);
                w[j].x += pf * s.x; w[j].y += pf * s.y;
                w[j].z += pf * s.z; w[j].w += pf * s.w;
            }
        }
        size_t off = ((size_t)b * DIM + f) * DIM + h * CH + dh;
        uint32_t* wh = (uint32_t*)(g_wh + off);
        uint32_t* wl = (uint32_t*)(g_wl + off);
#pragma unroll
        for (int j = 0; j < 6; j++) {
            uint32_t h0, l0, h1, l1;
            bsplit2(w[j].x, w[j].y, h0, l0);
            bsplit2(w[j].z, w[j].w, h1, l1);
            wh[2*j] = h0; wh[2*j+1] = h1;
            wl[2*j] = l0; wl[2*j+1] = l1;
        }
    }
}

// ---------------------------------------------------------------------------
extern "C" void kernel_launch(void* const* d_in, const int* in_sizes, int n_in,
                              void* d_out, int out_size)
{
    const float* x      = (const float*)d_in[0];
    const float* qkv_w  = (const float*)d_in[1];
    const float* temp   = (const float*)d_in[2];
    const float* proj_w = (const float*)d_in[3];
    const float* proj_b = (const float*)d_in[4];
    float* out = (float*)d_out;

    void *xh, *xl, *wqh, *wql;
    cudaGetSymbolAddress(&xh,  g_xh);
    cudaGetSymbolAddress(&xl,  g_xl);
    cudaGetSymbolAddress(&wqh, g_wqh);
    cudaGetSymbolAddress(&wql, g_wql);

    // 0) prepass: split x and qkv_w into bf16 h/l
    {
        int n4x = MTOT * KD / 4;
        split_kernel<<<(n4x + 255) / 256, 256>>>((const float4*)x, (uint2*)xh, (uint2*)xl, n4x);
        int n4w = ETOT * KD / 4;
        split_kernel<<<(n4w + 255) / 256, 256>>>((const float4*)qkv_w, (uint2*)wqh, (uint2*)wql, n4w);
    }

    cudaFuncSetAttribute(gemm_qkv_kernel,  cudaFuncAttributeMaxDynamicSharedMemorySize, GSMEM);
    cudaFuncSetAttribute(gemm_proj_kernel, cudaFuncAttributeMaxDynamicSharedMemorySize, GSMEM);

    // 1) qkv GEMM: q,k -> fp32 [e][m]; v -> transposed bf16 split [m][d]
    gemm_qkv_kernel<<<dim3(MTOT / 128, ETOT / 128), 256, GSMEM>>>();

    // 2) attention: partial QK + norms (512 blocks), then combine -> W_b bf16 split
    const int asmem = 2 * 48 * NTP * (int)sizeof(float);  // 50688
    cudaFuncSetAttribute(attn_part_kernel, cudaFuncAttributeMaxDynamicSharedMemorySize, asmem);
    attn_part_kernel<<<512, 256, asmem>>>();
    attn_combine_kernel<<<256, 256>>>(temp, proj_w);

    // 3) proj GEMM per batch: out = vT · W_b^T + bias
    gemm_proj_kernel<<<dim3(DIM / 128, (NTOK + 127) / 128, BATCH), 256, GSMEM>>>(proj_b, out);
}